// round 9
// baseline (speedup 1.0000x reference)
#include <cuda_runtime.h>
#include <math.h>

#define BB 2
#define LL 1000
#define DD 288
#define HH 8
#define DIMH 36
#define DFF_ 576
#define KS_ 250
#define NQ_ 250
#define BHN 16   // BB*HH
#define KSPLIT 4
#define FSPLIT 3   // ffn2 k-split

// ---------------- scratch (device globals; no allocs allowed) ----------------
__device__ __align__(16) float g_q[BHN*LL*DIMH];
__device__ __align__(16) float g_k[BHN*LL*DIMH];
__device__ __align__(16) float g_v[BHN*LL*DIMH];
__device__ __align__(16) float g_S[(size_t)BHN*LL*LL];      // 64 MB
__device__ float g_meas[BHN*LL];
__device__ int   g_idxq[BHN*NQ_];
__device__ int   g_inv[BHN*LL];
__device__ float g_m[BHN*NQ_];
__device__ float g_invs[BHN*NQ_];
__device__ float g_opart[(size_t)KSPLIT*BHN*NQ_*DIMH];
__device__ float g_vmean[BHN*DIMH];
__device__ __align__(16) float g_h1[BB*LL*DD];
__device__ __align__(16) float g_f1[BB*LL*DFF_];
__device__ __align__(16) float g_f2[(size_t)FSPLIT*BB*LL*DD];

// ---------------- f32x2 helpers ----------------
__device__ __forceinline__ void fma2(unsigned long long& d, unsigned long long a, unsigned long long b){
  asm("fma.rn.f32x2 %0, %1, %2, %3;" : "=l"(d) : "l"(a), "l"(b), "l"(d));
}
__device__ __forceinline__ float2 unpack2(unsigned long long v){
  float2 r; asm("mov.b64 {%0, %1}, %2;" : "=f"(r.x), "=f"(r.y) : "l"(v)); return r;
}

// ---------------- reduction helpers ----------------
__device__ __forceinline__ float warpRedSum(float v){
#pragma unroll
  for (int o=16;o;o>>=1) v += __shfl_xor_sync(0xffffffffu, v, o);
  return v;
}
__device__ __forceinline__ float warpRedMax(float v){
#pragma unroll
  for (int o=16;o;o>>=1) v = fmaxf(v, __shfl_xor_sync(0xffffffffu, v, o));
  return v;
}
__device__ float blockRedSum(float v, float* sm, int nwarp){
  int w = threadIdx.x >> 5, lane = threadIdx.x & 31;
  v = warpRedSum(v);
  if (lane == 0) sm[w] = v;
  __syncthreads();
  float r;
  if (w == 0){
    r = (lane < nwarp) ? sm[lane] : 0.f;
    r = warpRedSum(r);
    if (lane == 0) sm[0] = r;
  }
  __syncthreads();
  r = sm[0];
  __syncthreads();
  return r;
}

// ============ dense GEMM (f32x2): MTx96 tile, micro 8 rows x 3 col-pairs ============
// C = act(A[:, kStart:+kLen] @ W[:, kStart:+kLen]^T + bias). kLen%32==0, N%96==0.
// A duplicated in smem so LDS yields (a,a) packed; B column pairs natural.
template<int MT, int MODE, int GELU, int BIAS>
__device__ __forceinline__ void gemm_body(const float* __restrict__ A, const float* __restrict__ W,
                                          const float* __restrict__ bias, float* __restrict__ C,
                                          int M, int N, int lda, int kStart, int kLen){
  const int NT = 2*MT;               // threads
  const int ADW = (MT == 128) ? 260 : 132;   // dup A row width (mult of 4)
  const int NB = 768/NT;             // B float4 loads per thread
  __shared__ __align__(16) float As_dup[32][ADW];
  __shared__ __align__(16) float Bs[32][98];
  int tid = threadIdx.x;
  int m0 = blockIdx.y * MT, n0 = blockIdx.x * 96;
  int tx = tid & 15, ty = tid >> 4;
  unsigned long long acc[8][3];
#pragma unroll
  for (int i = 0; i < 8; i++)
#pragma unroll
    for (int j = 0; j < 3; j++) acc[i][j] = 0ull;
  float4 ra[4], rb[NB];
  const float4 z4 = make_float4(0.f,0.f,0.f,0.f);

#pragma unroll
  for (int it = 0; it < 4; it++){
    int i = tid + it*NT;
    int m = i >> 3, kv = i & 7;
    int gm = m0 + m;
    ra[it] = (gm < M) ? *(const float4*)(A + (size_t)gm*lda + kStart + 4*kv) : z4;
  }
#pragma unroll
  for (int it = 0; it < NB; it++){
    int i = tid + it*NT;
    int n = i >> 3, kv = i & 7;
    rb[it] = *(const float4*)(W + (size_t)(n0 + n)*lda + kStart + 4*kv);
  }
#pragma unroll
  for (int it = 0; it < 4; it++){
    int i = tid + it*NT;
    int m = i >> 3, kv = i & 7;
#pragma unroll
    for (int c = 0; c < 4; c++){
      float vv = (&ra[it].x)[c];
      As_dup[4*kv+c][2*m]   = vv;
      As_dup[4*kv+c][2*m+1] = vv;
    }
  }
#pragma unroll
  for (int it = 0; it < NB; it++){
    int i = tid + it*NT;
    int n = i >> 3, kv = i & 7;
    Bs[4*kv+0][n] = rb[it].x; Bs[4*kv+1][n] = rb[it].y;
    Bs[4*kv+2][n] = rb[it].z; Bs[4*kv+3][n] = rb[it].w;
  }
  __syncthreads();

  for (int k0 = 0; k0 < kLen; k0 += 32){
    bool more = (k0 + 32) < kLen;
    if (more){
      int kg = kStart + k0 + 32;
#pragma unroll
      for (int it = 0; it < 4; it++){
        int i = tid + it*NT;
        int m = i >> 3, kv = i & 7;
        int gm = m0 + m;
        ra[it] = (gm < M) ? *(const float4*)(A + (size_t)gm*lda + kg + 4*kv) : z4;
      }
#pragma unroll
      for (int it = 0; it < NB; it++){
        int i = tid + it*NT;
        int n = i >> 3, kv = i & 7;
        rb[it] = *(const float4*)(W + (size_t)(n0 + n)*lda + kg + 4*kv);
      }
    }
#pragma unroll 4
    for (int kk = 0; kk < 32; kk++){
      ulonglong2 x0 = *(const ulonglong2*)(&As_dup[kk][16*ty + 0]);
      ulonglong2 x1 = *(const ulonglong2*)(&As_dup[kk][16*ty + 4]);
      ulonglong2 x2 = *(const ulonglong2*)(&As_dup[kk][16*ty + 8]);
      ulonglong2 x3 = *(const ulonglong2*)(&As_dup[kk][16*ty + 12]);
      unsigned long long y0 = *(const unsigned long long*)(&Bs[kk][6*tx + 0]);
      unsigned long long y1 = *(const unsigned long long*)(&Bs[kk][6*tx + 2]);
      unsigned long long y2 = *(const unsigned long long*)(&Bs[kk][6*tx + 4]);
      unsigned long long X[8] = {x0.x,x0.y,x1.x,x1.y,x2.x,x2.y,x3.x,x3.y};
#pragma unroll
      for (int i = 0; i < 8; i++){
        fma2(acc[i][0], X[i], y0);
        fma2(acc[i][1], X[i], y1);
        fma2(acc[i][2], X[i], y2);
      }
    }
    __syncthreads();
    if (more){
#pragma unroll
      for (int it = 0; it < 4; it++){
        int i = tid + it*NT;
        int m = i >> 3, kv = i & 7;
#pragma unroll
        for (int c = 0; c < 4; c++){
          float vv = (&ra[it].x)[c];
          As_dup[4*kv+c][2*m]   = vv;
          As_dup[4*kv+c][2*m+1] = vv;
        }
      }
#pragma unroll
      for (int it = 0; it < NB; it++){
        int i = tid + it*NT;
        int n = i >> 3, kv = i & 7;
        Bs[4*kv+0][n] = rb[it].x; Bs[4*kv+1][n] = rb[it].y;
        Bs[4*kv+2][n] = rb[it].z; Bs[4*kv+3][n] = rb[it].w;
      }
      __syncthreads();
    }
  }
#pragma unroll
  for (int i = 0; i < 8; i++){
    int m = m0 + ty*8 + i;
    if (m >= M) continue;
#pragma unroll
    for (int jj = 0; jj < 3; jj++){
      float2 p = unpack2(acc[i][jj]);
#pragma unroll
      for (int c = 0; c < 2; c++){
        int n = n0 + tx*6 + 2*jj + c;
        float vv = (c == 0) ? p.x : p.y;
        if (BIAS) vv += bias[n];
        if (GELU) vv = 0.5f*vv*(1.0f + erff(vv*0.70710678118654752f));
        if (MODE == 0){
          C[(size_t)m*N + n] = vv;
        } else {
          int b_ = m / LL, l = m % LL;
          int h = n / DIMH, d = n % DIMH;
          C[(((size_t)b_*HH + h)*LL + l)*DIMH + d] = vv;
        }
      }
    }
  }
}

__global__ void __launch_bounds__(256) qkv_k(const float* __restrict__ x,
    const float* __restrict__ Wq, const float* __restrict__ bq,
    const float* __restrict__ Wk, const float* __restrict__ bk,
    const float* __restrict__ Wv, const float* __restrict__ bv,
    float* pq, float* pk, float* pv){
  const float* W; const float* b; float* C;
  if (blockIdx.z == 0){ W = Wq; b = bq; C = pq; }
  else if (blockIdx.z == 1){ W = Wk; b = bk; C = pk; }
  else { W = Wv; b = bv; C = pv; }
  gemm_body<128,1,0,1>(x, W, b, C, BB*LL, DD, DD, 0, DD);
}

__global__ void __launch_bounds__(128) ffn1_k(const float* __restrict__ A, const float* __restrict__ W,
                                              const float* __restrict__ bias, float* __restrict__ C){
  gemm_body<64,0,1,1>(A, W, bias, C, BB*LL, DFF_, DD, 0, DD);
}

__global__ void __launch_bounds__(256) ffn2_k(const float* __restrict__ A, const float* __restrict__ W,
                                              float* __restrict__ C){
  int ks = blockIdx.z;
  const int kLen = DFF_/FSPLIT;   // 192
  gemm_body<128,0,0,0>(A, W, nullptr, C + (size_t)ks*BB*LL*DD, BB*LL, DD, DFF_, ks*kLen, kLen);
}

// ---------------- S = Q K^T per (b,h), f32x2: 96(q) x 128(k) tile ----------------
// Q transposed + duplicated; K transposed with skew phys(c) = c + 4*(c>>5).
__global__ void __launch_bounds__(256) sgemm128(){
  __shared__ __align__(16) float QsT_dup[DIMH][192];
  __shared__ __align__(16) float KsT[DIMH][140];
  int bh = blockIdx.z;
  int q0 = blockIdx.y*96, k0 = blockIdx.x*128;
  const float* Q  = g_q + (size_t)bh*LL*DIMH;
  const float* Kp = g_k + (size_t)bh*LL*DIMH;
  int tid = threadIdx.x;
  const float4 z4 = make_float4(0.f,0.f,0.f,0.f);
  // Q: 96 rows x 9 float4 = 864
  for (int i = tid; i < 864; i += 256){
    int r = i / 9, dv = i % 9;
    int gq = q0 + r;
    float4 vq = (gq < LL) ? *(const float4*)(Q + (size_t)gq*DIMH + 4*dv) : z4;
#pragma unroll
    for (int c = 0; c < 4; c++){
      float vv = (&vq.x)[c];
      QsT_dup[4*dv+c][2*r]   = vv;
      QsT_dup[4*dv+c][2*r+1] = vv;
    }
  }
  // K: 128 rows x 9 float4 = 1152, skewed columns
  for (int i = tid; i < 1152; i += 256){
    int r = i / 9, dv = i % 9;
    int gk = k0 + r;
    float4 vk = (gk < LL) ? *(const float4*)(Kp + (size_t)gk*DIMH + 4*dv) : z4;
    int pc = r + 4*(r >> 5);
#pragma unroll
    for (int c = 0; c < 4; c++)
      KsT[4*dv+c][pc] = (&vk.x)[c];
  }
  __syncthreads();
  int tx = tid & 15, ty = tid >> 4;
  int cb = 8*tx + 4*(tx >> 2);   // skewed base col for this thread's 8 k-columns
  unsigned long long acc[6][4];
#pragma unroll
  for (int i = 0; i < 6; i++)
#pragma unroll
    for (int j = 0; j < 4; j++) acc[i][j] = 0ull;
#pragma unroll 4
  for (int d = 0; d < DIMH; d++){
    ulonglong2 x0 = *(const ulonglong2*)(&QsT_dup[d][12*ty + 0]);
    ulonglong2 x1 = *(const ulonglong2*)(&QsT_dup[d][12*ty + 4]);
    ulonglong2 x2 = *(const ulonglong2*)(&QsT_dup[d][12*ty + 8]);
    unsigned long long y0 = *(const unsigned long long*)(&KsT[d][cb + 0]);
    unsigned long long y1 = *(const unsigned long long*)(&KsT[d][cb + 2]);
    unsigned long long y2 = *(const unsigned long long*)(&KsT[d][cb + 4]);
    unsigned long long y3 = *(const unsigned long long*)(&KsT[d][cb + 6]);
    unsigned long long X[6] = {x0.x,x0.y,x1.x,x1.y,x2.x,x2.y};
#pragma unroll
    for (int i = 0; i < 6; i++){
      fma2(acc[i][0], X[i], y0);
      fma2(acc[i][1], X[i], y1);
      fma2(acc[i][2], X[i], y2);
      fma2(acc[i][3], X[i], y3);
    }
  }
  float* Sp = g_S + (size_t)bh*LL*LL;
  bool fullcol = (k0 + tx*8 + 7) < LL;
#pragma unroll
  for (int i = 0; i < 6; i++){
    int m = q0 + ty*6 + i;
    if (m >= LL) continue;
    float2 p0 = unpack2(acc[i][0]), p1 = unpack2(acc[i][1]);
    float2 p2 = unpack2(acc[i][2]), p3 = unpack2(acc[i][3]);
    float* dst = Sp + (size_t)m*LL + k0 + tx*8;
    if (fullcol){
      *(float4*)dst     = make_float4(p0.x,p0.y,p1.x,p1.y);
      *(float4*)(dst+4) = make_float4(p2.x,p2.y,p3.x,p3.y);
    } else {
      float vv[8] = {p0.x,p0.y,p1.x,p1.y,p2.x,p2.y,p3.x,p3.y};
#pragma unroll
      for (int j = 0; j < 8; j++)
        if (k0 + tx*8 + j < LL) dst[j] = vv[j];
    }
  }
}

// ---------------- measure (warp/row) ----------------
__global__ void measure_k(const int* __restrict__ ik){
  int w = threadIdx.x >> 5, lane = threadIdx.x & 31;
  int l = blockIdx.x*8 + w, bh = blockIdx.y;
  if (l >= LL) return;
  const float* Srow = g_S + ((size_t)bh*LL + l)*LL;
  const int* row = ik + l*KS_;
  float mx = -INFINITY, s = 0.f;
  for (int j = lane; j < KS_; j += 32){
    float vv = Srow[row[j]];
    mx = fmaxf(mx, vv); s += vv;
  }
  mx = warpRedMax(mx);
  s  = warpRedSum(s);
  if (lane == 0) g_meas[bh*LL + l] = mx - s * (1.0f/(float)LL);
}

// ---------------- top-NQ per (b,h): register radix select, scan-based gather ----------------
__global__ void __launch_bounds__(256) topk_k(){
  __shared__ int hist[256];
  __shared__ int warpbase[9];
  __shared__ int s_digit, s_r;
  int bh = blockIdx.x, tid = threadIdx.x;
  bool real = tid < 250;
  unsigned kv[4] = {0,0,0,0};
  if (real){
#pragma unroll
    for (int j = 0; j < 4; j++){
      unsigned u = __float_as_uint(g_meas[bh*LL + 4*tid + j]);
      kv[j] = (u & 0x80000000u) ? ~u : (u | 0x80000000u);
    }
  }
  hist[tid] = 0;
  __syncthreads();
  unsigned prefix = 0; int r = NQ_;
#pragma unroll
  for (int pass = 0; pass < 4; pass++){
    int shift = 24 - pass*8;
    if (real){
#pragma unroll
      for (int j = 0; j < 4; j++){
        unsigned u = kv[j];
        if (pass == 0 || (u >> (shift + 8)) == prefix)
          atomicAdd(&hist[(u >> shift) & 255], 1);
      }
    }
    __syncthreads();
    if (tid < 32){
      int b[8], suf[8]; int acc = 0;
#pragma unroll
      for (int j = 7; j >= 0; j--){ b[j] = hist[tid*8 + j]; acc += b[j]; suf[j] = acc; }
      int inc = acc;
#pragma unroll
      for (int off = 1; off < 32; off <<= 1){
        int t = __shfl_down_sync(0xffffffffu, inc, off);
        if (tid + off < 32) inc += t;
      }
      int hiex = inc - acc;
#pragma unroll
      for (int j = 0; j < 8; j++){
        int ge = suf[j] + hiex;
        int gt = ge - b[j];
        if (gt < r && r <= ge){ s_digit = tid*8 + j; s_r = r - gt; }
      }
    }
    __syncthreads();
    prefix = (prefix << 8) | (unsigned)s_digit;
    r = s_r;
    hist[tid] = 0;
    __syncthreads();
  }
  unsigned T = prefix;
  int cg = 0, ce = 0; int locg[4], loce[4];
  if (real){
#pragma unroll
    for (int j = 0; j < 4; j++){
      locg[j] = cg; loce[j] = ce;
      cg += (kv[j] > T); ce += (kv[j] == T);
    }
  }
  int pack = (cg << 16) | ce;
  int lane = tid & 31, w = tid >> 5;
  int sc = pack;
#pragma unroll
  for (int off = 1; off < 32; off <<= 1){
    int t = __shfl_up_sync(0xffffffffu, sc, off);
    if (lane >= off) sc += t;
  }
  if (lane == 31) warpbase[w+1] = sc;
  if (tid == 0) warpbase[0] = 0;
  __syncthreads();
  if (tid == 0){ for (int i = 1; i < 8; i++) warpbase[i+1] += warpbase[i]; }
  __syncthreads();
  int excl = sc - pack + warpbase[w];
  int eg = excl >> 16, ee = excl & 0xffff;
  if (real){
#pragma unroll
    for (int j = 0; j < 4; j++){
      int i = 4*tid + j;
      int pos = -1;
      if (kv[j] > T) pos = eg + locg[j];
      else if (kv[j] == T){
        int rk = ee + loce[j];
        if (rk < r) pos = (NQ_ - r) + rk;
      }
      g_inv[bh*LL + i] = pos;
      if (pos >= 0) g_idxq[bh*NQ_ + pos] = i;
    }
  }
}

// ---------------- per-selected-query softmax stats ----------------
__global__ void msum_k(){
  int tid = threadIdx.x;
  int w = tid >> 5, lane = tid & 31;
  int q = blockIdx.x*8 + w;
  int bh = blockIdx.y;
  if (q >= NQ_) return;
  const float sc = 1.0f/6.0f;
  int lq = g_idxq[bh*NQ_ + q];
  const float* row = g_S + ((size_t)bh*LL + lq)*LL;
  float mx = -INFINITY;
  for (int i = lane; i < LL; i += 32) mx = fmaxf(mx, row[i]);
  mx = warpRedMax(mx);
  float m = mx * sc;
  float s = 0.f;
  for (int i = lane; i < LL; i += 32) s += __expf(row[i]*sc - m);
  s = warpRedSum(s);
  if (lane == 0){ g_m[bh*NQ_ + q] = m; g_invs[bh*NQ_ + q] = 1.0f/s; }
}

// ---------------- fused softmax+PV, k-split partials ----------------
__global__ void __launch_bounds__(256) spv_k(){
  __shared__ float Ps[64][65];
  __shared__ float Vs[64][37];
  __shared__ float mS[64], invS[64];
  __shared__ int   lqS[64];
  int tid = threadIdx.x;
  int q0 = blockIdx.x*64;
  int ksb = blockIdx.y;
  int bh = blockIdx.z;
  int kstart = ksb*(LL/KSPLIT), kend = kstart + (LL/KSPLIT);
  const float sc = 1.0f/6.0f;
  if (tid < 64){
    int gq = q0 + tid;
    if (gq < NQ_){
      lqS[tid] = g_idxq[bh*NQ_ + gq];
      mS[tid]  = g_m[bh*NQ_ + gq];
      invS[tid]= g_invs[bh*NQ_ + gq];
    } else { lqS[tid]=0; mS[tid]=0.f; invS[tid]=0.f; }
  }
  __syncthreads();
  const float* Vp = g_v + (size_t)bh*LL*DIMH;
  const float* Sbh = g_S + (size_t)bh*LL*LL;
  int r = tid >> 2, cg = tid & 3;
  float acc[9] = {};
  for (int k0 = kstart; k0 < kend; k0 += 64){
    for (int i = tid; i < 64*DIMH; i += 256){
      int rr = i / DIMH, d = i % DIMH;
      int kr = k0 + rr;
      Vs[rr][d] = (kr < kend) ? Vp[(size_t)kr*DIMH + d] : 0.f;
    }
    for (int i = tid; i < 4096; i += 256){
      int qq = i >> 6, kk = i & 63;
      int kr = k0 + kk;
      float val = 0.f;
      if (q0 + qq < NQ_ && kr < kend)
        val = __expf(Sbh[(size_t)lqS[qq]*LL + kr]*sc - mS[qq]) * invS[qq];
      Ps[qq][kk] = val;
    }
    __syncthreads();
#pragma unroll 4
    for (int kk = 0; kk < 64; kk++){
      float p = Ps[r][kk];
#pragma unroll
      for (int c = 0; c < 9; c++) acc[c] += p * Vs[kk][cg*9 + c];
    }
    __syncthreads();
  }
  if (q0 + r < NQ_){
    float* dst = g_opart + (((size_t)ksb*BHN + bh)*NQ_ + q0 + r)*DIMH + cg*9;
#pragma unroll
    for (int c = 0; c < 9; c++) dst[c] = acc[c];
  }
}

// ---------------- vmean ----------------
__global__ void vmean_k(){
  __shared__ float sm[32];
  int d = blockIdx.x, bh = blockIdx.y, t = threadIdx.x;
  float s = 0.f;
  for (int l = t; l < LL; l += 256) s += g_v[((size_t)bh*LL + l)*DIMH + d];
  s = blockRedSum(s, sm, 8);
  if (t == 0) g_vmean[bh*DIMH + d] = s * (1.0f/(float)LL);
}

// ---------------- LN1 fused: gather attn + x, then LN ----------------
__global__ void ln1f_kernel(const float* __restrict__ x,
                            const float* __restrict__ gamma, const float* __restrict__ beta,
                            float* __restrict__ out){
  __shared__ float sm[32];
  int row = blockIdx.x, t = threadIdx.x;
  int b_ = row / LL, l = row % LL;
  int h = t / DIMH, d = t % DIMH;
  int bh = b_*HH + h;
  int qi = g_inv[bh*LL + l];
  float attn;
  if (qi >= 0){
    attn = 0.f;
#pragma unroll
    for (int ks = 0; ks < KSPLIT; ks++)
      attn += g_opart[(((size_t)ks*BHN + bh)*NQ_ + qi)*DIMH + d];
  } else {
    attn = g_vmean[bh*DIMH + d];
  }
  float s = x[(size_t)row*DD + t] + attn;
  float mu = blockRedSum(s, sm, 9) * (1.0f/(float)DD);
  float dd = s - mu;
  float var = blockRedSum(dd*dd, sm, 9) * (1.0f/(float)DD);
  out[(size_t)row*DD + t] = dd * rsqrtf(var + 1e-5f) * gamma[t] + beta[t];
}

// ---------------- LN2: sum ffn2 partials + bias -> GELU -> +h1 -> LN ----------------
__global__ void ln2_kernel(const float* __restrict__ f2p, const float* __restrict__ b2,
                           const float* __restrict__ h1,
                           const float* __restrict__ gamma, const float* __restrict__ beta,
                           float* __restrict__ out){
  __shared__ float sm[32];
  int row = blockIdx.x, t = threadIdx.x;
  size_t o = (size_t)row*DD + t;
  const size_t stride = (size_t)BB*LL*DD;
  float v = f2p[o] + f2p[stride + o] + f2p[2*stride + o] + b2[t];
  v = 0.5f*v*(1.0f + erff(v*0.70710678118654752f));
  float s = v + h1[o];
  float mu = blockRedSum(s, sm, 9) * (1.0f/(float)DD);
  float d = s - mu;
  float var = blockRedSum(d*d, sm, 9) * (1.0f/(float)DD);
  out[o] = d * rsqrtf(var + 1e-5f) * gamma[t] + beta[t];
}

// ---------------- launch ----------------
extern "C" void kernel_launch(void* const* d_in, const int* in_sizes, int n_in,
                              void* d_out, int out_size){
  const float* x  = (const float*)d_in[0];
  const int*   ik = (const int*)  d_in[1];
  const float* Wq = (const float*)d_in[2];  const float* bq = (const float*)d_in[3];
  const float* Wk = (const float*)d_in[4];  const float* bk = (const float*)d_in[5];
  const float* Wv = (const float*)d_in[6];  const float* bv = (const float*)d_in[7];
  const float* W1 = (const float*)d_in[8];  const float* b1 = (const float*)d_in[9];
  const float* W2 = (const float*)d_in[10]; const float* b2 = (const float*)d_in[11];
  const float* g1 = (const float*)d_in[12]; const float* be1 = (const float*)d_in[13];
  const float* g2 = (const float*)d_in[14]; const float* be2 = (const float*)d_in[15];
  float* out = (float*)d_out;

  float *pq, *pk, *pv, *ph1, *pf1, *pf2;
  cudaGetSymbolAddress((void**)&pq,   g_q);
  cudaGetSymbolAddress((void**)&pk,   g_k);
  cudaGetSymbolAddress((void**)&pv,   g_v);
  cudaGetSymbolAddress((void**)&ph1,  g_h1);
  cudaGetSymbolAddress((void**)&pf1,  g_f1);
  cudaGetSymbolAddress((void**)&pf2,  g_f2);

  const int M = BB*LL;  // 2000
  qkv_k<<<dim3(DD/96, (M + 127)/128, 3), 256>>>(x, Wq, bq, Wk, bk, Wv, bv, pq, pk, pv);

  sgemm128<<<dim3(8, 11, BHN), 256>>>();
  measure_k<<<dim3((LL + 7)/8, BHN), 256>>>(ik);
  topk_k<<<BHN, 256>>>();
  msum_k<<<dim3((NQ_ + 7)/8, BHN), 256>>>();
  spv_k<<<dim3((NQ_ + 63)/64, KSPLIT, BHN), 256>>>();
  vmean_k<<<dim3(DIMH, BHN), 256>>>();

  ln1f_kernel<<<M, DD>>>(x, g1, be1, ph1);

  ffn1_k<<<dim3(DFF_/96, (M + 63)/64), 128>>>(ph1, W1, b1, pf1);
  ffn2_k<<<dim3(DD/96, (M + 127)/128, FSPLIT), 256>>>(pf1, W2, pf2);

  ln2_kernel<<<M, DD>>>(pf2, b2, ph1, g2, be2, out);
}

// round 12
// speedup vs baseline: 1.0769x; 1.0769x over previous
#include <cuda_runtime.h>
#include <math.h>

#define BB 2
#define LL 1000
#define DD 288
#define HH 8
#define DIMH 36
#define DFF_ 576
#define KS_ 250
#define NQ_ 250
#define BHN 16   // BB*HH
#define KSPLIT 4
#define FSPLIT 3   // ffn2 k-split

// ---------------- scratch (device globals; no allocs allowed) ----------------
__device__ __align__(16) float g_q[BHN*LL*DIMH];
__device__ __align__(16) float g_k[BHN*LL*DIMH];
__device__ __align__(16) float g_v[BHN*LL*DIMH];
__device__ __align__(16) float g_S[(size_t)BHN*LL*LL];      // 64 MB
__device__ float g_meas[BHN*LL];
__device__ int   g_idxq[BHN*NQ_];
__device__ int   g_inv[BHN*LL];
__device__ float g_opart[(size_t)KSPLIT*BHN*NQ_*DIMH];
__device__ float g_ms[KSPLIT*BHN*NQ_];
__device__ float g_ss[KSPLIT*BHN*NQ_];
__device__ float g_vmean[BHN*DIMH];
__device__ __align__(16) float g_h1[BB*LL*DD];
__device__ __align__(16) float g_f1[BB*LL*DFF_];
__device__ __align__(16) float g_f2[(size_t)FSPLIT*BB*LL*DD];

// ---------------- reduction helpers ----------------
__device__ __forceinline__ float warpRedSum(float v){
#pragma unroll
  for (int o=16;o;o>>=1) v += __shfl_xor_sync(0xffffffffu, v, o);
  return v;
}
__device__ __forceinline__ float warpRedMax(float v){
#pragma unroll
  for (int o=16;o;o>>=1) v = fmaxf(v, __shfl_xor_sync(0xffffffffu, v, o));
  return v;
}
__device__ float blockRedSum(float v, float* sm, int nwarp){
  int w = threadIdx.x >> 5, lane = threadIdx.x & 31;
  v = warpRedSum(v);
  if (lane == 0) sm[w] = v;
  __syncthreads();
  float r;
  if (w == 0){
    r = (lane < nwarp) ? sm[lane] : 0.f;
    r = warpRedSum(r);
    if (lane == 0) sm[0] = r;
  }
  __syncthreads();
  r = sm[0];
  __syncthreads();
  return r;
}
// single-pass (sum, sumsq) block reduction
__device__ float2 blockRedSum2(float a, float b, float2* sm, int nwarp){
  int w = threadIdx.x >> 5, lane = threadIdx.x & 31;
#pragma unroll
  for (int o=16;o;o>>=1){
    a += __shfl_xor_sync(0xffffffffu, a, o);
    b += __shfl_xor_sync(0xffffffffu, b, o);
  }
  if (lane == 0) sm[w] = make_float2(a, b);
  __syncthreads();
  float2 r;
  if (w == 0){
    float ra = (lane < nwarp) ? sm[lane].x : 0.f;
    float rb = (lane < nwarp) ? sm[lane].y : 0.f;
#pragma unroll
    for (int o=16;o;o>>=1){
      ra += __shfl_xor_sync(0xffffffffu, ra, o);
      rb += __shfl_xor_sync(0xffffffffu, rb, o);
    }
    if (lane == 0) sm[0] = make_float2(ra, rb);
  }
  __syncthreads();
  r = sm[0];
  __syncthreads();
  return r;
}

// ============ dense GEMM: MTx96 tile (MT in {64,128}), 8x6 micro, 2*MT threads ============
template<int MT, int MODE, int GELU, int BIAS>
__device__ __forceinline__ void gemm_body(const float* __restrict__ A, const float* __restrict__ W,
                                          const float* __restrict__ bias, float* __restrict__ C,
                                          int M, int N, int lda, int kStart, int kLen){
  const int NT = 2*MT;          // threads
  const int RS = MT/8;          // row stride in micro loop
  const int NB = 384/MT;        // B float4 loads per thread
  __shared__ __align__(16) float As[MT][36];   // [m][kk] 32 used
  __shared__ float Bs[32][97];                 // [kk][n]
  int tid = threadIdx.x;
  int m0 = blockIdx.y * MT, n0 = blockIdx.x * 96;
  int tx = tid & 15, ty = tid >> 4;
  float acc[8][6] = {};
  float4 ra[4], rb[NB];
  const float4 z4 = make_float4(0.f,0.f,0.f,0.f);

#pragma unroll
  for (int it = 0; it < 4; it++){
    int i = tid + it*NT;
    int m = i >> 3, kv = i & 7;
    int gm = m0 + m;
    ra[it] = (gm < M) ? *(const float4*)(A + (size_t)gm*lda + kStart + 4*kv) : z4;
  }
#pragma unroll
  for (int it = 0; it < NB; it++){
    int i = tid + it*NT;
    int n = i >> 3, kv = i & 7;
    rb[it] = *(const float4*)(W + (size_t)(n0 + n)*lda + kStart + 4*kv);
  }
#pragma unroll
  for (int it = 0; it < 4; it++){
    int i = tid + it*NT;
    int m = i >> 3, kv = i & 7;
    *(float4*)(&As[m][4*kv]) = ra[it];
  }
#pragma unroll
  for (int it = 0; it < NB; it++){
    int i = tid + it*NT;
    int n = i >> 3, kv = i & 7;
    Bs[4*kv+0][n] = rb[it].x; Bs[4*kv+1][n] = rb[it].y;
    Bs[4*kv+2][n] = rb[it].z; Bs[4*kv+3][n] = rb[it].w;
  }
  __syncthreads();

  for (int k0 = 0; k0 < kLen; k0 += 32){
    bool more = (k0 + 32) < kLen;
    if (more){
      int kg = kStart + k0 + 32;
#pragma unroll
      for (int it = 0; it < 4; it++){
        int i = tid + it*NT;
        int m = i >> 3, kv = i & 7;
        int gm = m0 + m;
        ra[it] = (gm < M) ? *(const float4*)(A + (size_t)gm*lda + kg + 4*kv) : z4;
      }
#pragma unroll
      for (int it = 0; it < NB; it++){
        int i = tid + it*NT;
        int n = i >> 3, kv = i & 7;
        rb[it] = *(const float4*)(W + (size_t)(n0 + n)*lda + kg + 4*kv);
      }
    }
#pragma unroll 4
    for (int kk = 0; kk < 32; kk++){
      float a[8], b[6];
#pragma unroll
      for (int i = 0; i < 8; i++) a[i] = As[ty + RS*i][kk];
#pragma unroll
      for (int j = 0; j < 6; j++) b[j] = Bs[kk][tx*6+j];
#pragma unroll
      for (int i = 0; i < 8; i++)
#pragma unroll
        for (int j = 0; j < 6; j++) acc[i][j] += a[i]*b[j];
    }
    __syncthreads();
    if (more){
#pragma unroll
      for (int it = 0; it < 4; it++){
        int i = tid + it*NT;
        int m = i >> 3, kv = i & 7;
        *(float4*)(&As[m][4*kv]) = ra[it];
      }
#pragma unroll
      for (int it = 0; it < NB; it++){
        int i = tid + it*NT;
        int n = i >> 3, kv = i & 7;
        Bs[4*kv+0][n] = rb[it].x; Bs[4*kv+1][n] = rb[it].y;
        Bs[4*kv+2][n] = rb[it].z; Bs[4*kv+3][n] = rb[it].w;
      }
      __syncthreads();
    }
  }
#pragma unroll
  for (int i = 0; i < 8; i++){
    int m = m0 + ty + RS*i;
    if (m >= M) continue;
#pragma unroll
    for (int j = 0; j < 6; j++){
      int n = n0 + tx*6 + j;
      float vv = acc[i][j];
      if (BIAS) vv += bias[n];
      if (GELU) vv = 0.5f*vv*(1.0f + erff(vv*0.70710678118654752f));
      if (MODE == 0){
        C[(size_t)m*N + n] = vv;
      } else {
        int b_ = m / LL, l = m % LL;
        int h = n / DIMH, d = n % DIMH;
        C[(((size_t)b_*HH + h)*LL + l)*DIMH + d] = vv;
      }
    }
  }
}

__global__ void __launch_bounds__(256) qkv_k(const float* __restrict__ x,
    const float* __restrict__ Wq, const float* __restrict__ bq,
    const float* __restrict__ Wk, const float* __restrict__ bk,
    const float* __restrict__ Wv, const float* __restrict__ bv,
    float* pq, float* pk, float* pv){
  const float* W; const float* b; float* C;
  if (blockIdx.z == 0){ W = Wq; b = bq; C = pq; }
  else if (blockIdx.z == 1){ W = Wk; b = bk; C = pk; }
  else { W = Wv; b = bv; C = pv; }
  gemm_body<128,1,0,1>(x, W, b, C, BB*LL, DD, DD, 0, DD);
}

__global__ void __launch_bounds__(128) ffn1_k(const float* __restrict__ A, const float* __restrict__ W,
                                              const float* __restrict__ bias, float* __restrict__ C){
  gemm_body<64,0,1,1>(A, W, bias, C, BB*LL, DFF_, DD, 0, DD);
}

__global__ void __launch_bounds__(256) ffn2_k(const float* __restrict__ A, const float* __restrict__ W,
                                              float* __restrict__ C){
  int ks = blockIdx.z;
  const int kLen = DFF_/FSPLIT;   // 192
  gemm_body<128,0,0,0>(A, W, nullptr, C + (size_t)ks*BB*LL*DD, BB*LL, DD, DFF_, ks*kLen, kLen);
}

// ---------------- S = Q K^T per (b,h): 128x128 tile, 8x8 micro ----------------
__global__ void __launch_bounds__(256) sgemm128(){
  __shared__ __align__(16) float QsT[DIMH][132];
  __shared__ __align__(16) float KsT[DIMH][132];
  int bh = blockIdx.z;
  int q0 = blockIdx.y*128, k0 = blockIdx.x*128;
  const float* Q  = g_q + (size_t)bh*LL*DIMH;
  const float* Kp = g_k + (size_t)bh*LL*DIMH;
  int tid = threadIdx.x;
  const float4 z4 = make_float4(0.f,0.f,0.f,0.f);
  for (int i = tid; i < 1152; i += 256){
    int r = i / 9, dv = i % 9;
    int gq = q0 + r, gk = k0 + r;
    float4 vq = (gq < LL) ? *(const float4*)(Q  + (size_t)gq*DIMH + 4*dv) : z4;
    float4 vk = (gk < LL) ? *(const float4*)(Kp + (size_t)gk*DIMH + 4*dv) : z4;
    QsT[4*dv+0][r] = vq.x; QsT[4*dv+1][r] = vq.y; QsT[4*dv+2][r] = vq.z; QsT[4*dv+3][r] = vq.w;
    KsT[4*dv+0][r] = vk.x; KsT[4*dv+1][r] = vk.y; KsT[4*dv+2][r] = vk.z; KsT[4*dv+3][r] = vk.w;
  }
  __syncthreads();
  int tx = tid & 15, ty = tid >> 4;
  float acc[8][8] = {};
#pragma unroll 4
  for (int d = 0; d < DIMH; d++){
    float4 a0 = *(const float4*)(&QsT[d][ty*8]);
    float4 a1 = *(const float4*)(&QsT[d][ty*8+4]);
    float4 b0 = *(const float4*)(&KsT[d][tx*8]);
    float4 b1 = *(const float4*)(&KsT[d][tx*8+4]);
    float a[8] = {a0.x,a0.y,a0.z,a0.w,a1.x,a1.y,a1.z,a1.w};
    float b[8] = {b0.x,b0.y,b0.z,b0.w,b1.x,b1.y,b1.z,b1.w};
#pragma unroll
    for (int i = 0; i < 8; i++)
#pragma unroll
      for (int j = 0; j < 8; j++) acc[i][j] += a[i]*b[j];
  }
  float* Sp = g_S + (size_t)bh*LL*LL;
  bool fullcol = (k0 + tx*8 + 7) < LL;
#pragma unroll
  for (int i = 0; i < 8; i++){
    int m = q0 + ty*8 + i;
    if (m >= LL) continue;
    float* dst = Sp + (size_t)m*LL + k0 + tx*8;
    if (fullcol){
      *(float4*)dst      = make_float4(acc[i][0],acc[i][1],acc[i][2],acc[i][3]);
      *(float4*)(dst+4)  = make_float4(acc[i][4],acc[i][5],acc[i][6],acc[i][7]);
    } else {
#pragma unroll
      for (int j = 0; j < 8; j++)
        if (k0 + tx*8 + j < LL) dst[j] = acc[i][j];
    }
  }
}

// ---------------- measure (warp/row) ----------------
__global__ void measure_k(const int* __restrict__ ik){
  int w = threadIdx.x >> 5, lane = threadIdx.x & 31;
  int l = blockIdx.x*8 + w, bh = blockIdx.y;
  if (l >= LL) return;
  const float* Srow = g_S + ((size_t)bh*LL + l)*LL;
  const int* row = ik + l*KS_;
  float mx = -INFINITY, s = 0.f;
  for (int j = lane; j < KS_; j += 32){
    float vv = Srow[row[j]];
    mx = fmaxf(mx, vv); s += vv;
  }
  mx = warpRedMax(mx);
  s  = warpRedSum(s);
  if (lane == 0) g_meas[bh*LL + l] = mx - s * (1.0f/(float)LL);
}

// ---------------- top-NQ per (b,h): register radix select, scan-based gather ----------------
__global__ void __launch_bounds__(256) topk_k(){
  __shared__ int hist[256];
  __shared__ int warpbase[9];
  __shared__ int s_digit, s_r;
  int bh = blockIdx.x, tid = threadIdx.x;
  bool real = tid < 250;
  unsigned kv[4] = {0,0,0,0};
  if (real){
#pragma unroll
    for (int j = 0; j < 4; j++){
      unsigned u = __float_as_uint(g_meas[bh*LL + 4*tid + j]);
      kv[j] = (u & 0x80000000u) ? ~u : (u | 0x80000000u);
    }
  }
  hist[tid] = 0;
  __syncthreads();
  unsigned prefix = 0; int r = NQ_;
#pragma unroll
  for (int pass = 0; pass < 4; pass++){
    int shift = 24 - pass*8;
    if (real){
#pragma unroll
      for (int j = 0; j < 4; j++){
        unsigned u = kv[j];
        if (pass == 0 || (u >> (shift + 8)) == prefix)
          atomicAdd(&hist[(u >> shift) & 255], 1);
      }
    }
    __syncthreads();
    if (tid < 32){
      int b[8], suf[8]; int acc = 0;
#pragma unroll
      for (int j = 7; j >= 0; j--){ b[j] = hist[tid*8 + j]; acc += b[j]; suf[j] = acc; }
      int inc = acc;
#pragma unroll
      for (int off = 1; off < 32; off <<= 1){
        int t = __shfl_down_sync(0xffffffffu, inc, off);
        if (tid + off < 32) inc += t;
      }
      int hiex = inc - acc;
#pragma unroll
      for (int j = 0; j < 8; j++){
        int ge = suf[j] + hiex;
        int gt = ge - b[j];
        if (gt < r && r <= ge){ s_digit = tid*8 + j; s_r = r - gt; }
      }
    }
    __syncthreads();
    prefix = (prefix << 8) | (unsigned)s_digit;
    r = s_r;
    hist[tid] = 0;
    __syncthreads();
  }
  unsigned T = prefix;
  int cg = 0, ce = 0; int locg[4], loce[4];
  if (real){
#pragma unroll
    for (int j = 0; j < 4; j++){
      locg[j] = cg; loce[j] = ce;
      cg += (kv[j] > T); ce += (kv[j] == T);
    }
  }
  int pack = (cg << 16) | ce;
  int lane = tid & 31, w = tid >> 5;
  int sc = pack;
#pragma unroll
  for (int off = 1; off < 32; off <<= 1){
    int t = __shfl_up_sync(0xffffffffu, sc, off);
    if (lane >= off) sc += t;
  }
  if (lane == 31) warpbase[w+1] = sc;
  if (tid == 0) warpbase[0] = 0;
  __syncthreads();
  if (tid == 0){ for (int i = 1; i < 8; i++) warpbase[i+1] += warpbase[i]; }
  __syncthreads();
  int excl = sc - pack + warpbase[w];
  int eg = excl >> 16, ee = excl & 0xffff;
  if (real){
#pragma unroll
    for (int j = 0; j < 4; j++){
      int i = 4*tid + j;
      int pos = -1;
      if (kv[j] > T) pos = eg + locg[j];
      else if (kv[j] == T){
        int rk = ee + loce[j];
        if (rk < r) pos = (NQ_ - r) + rk;
      }
      g_inv[bh*LL + i] = pos;
      if (pos >= 0) g_idxq[bh*NQ_ + pos] = i;
    }
  }
}

// ---------------- fused ONLINE softmax + PV per k-split (bounds-guarded) ----------------
__global__ void __launch_bounds__(256) spv_k(){
  __shared__ float Ps[64][65];
  __shared__ float Vs[64][37];
  __shared__ float rowm[64];
  __shared__ int   lqS[64];
  int tid = threadIdx.x;
  int q0 = blockIdx.x*64;
  int ksb = blockIdx.y;
  int bh = blockIdx.z;
  int kstart = ksb*(LL/KSPLIT), kend = kstart + (LL/KSPLIT);
  const float sc = 1.0f/6.0f;
  if (tid < 64){
    int gq = q0 + tid;
    lqS[tid] = (gq < NQ_) ? g_idxq[bh*NQ_ + gq] : 0;
  }
  __syncthreads();
  const float* Vp = g_v + (size_t)bh*LL*DIMH;
  const float* Sbh = g_S + (size_t)bh*LL*LL;
  int r = tid >> 2, cg = tid & 3;
  // phase 1: per-row max over this split's columns (4 threads per row)
  {
    const float* row = Sbh + (size_t)lqS[r]*LL;
    float mx = -INFINITY;
    for (int c = kstart + cg; c < kend; c += 4) mx = fmaxf(mx, row[c]);
    mx = fmaxf(mx, __shfl_xor_sync(0xffffffffu, mx, 1));
    mx = fmaxf(mx, __shfl_xor_sync(0xffffffffu, mx, 2));
    if (cg == 0) rowm[r] = mx * sc;
  }
  __syncthreads();
  // phase 2: exp + PV accumulate + row sum (columns >= kend masked to 0)
  float acc[9] = {};
  float ssum = 0.f;
  for (int k0 = kstart; k0 < kend; k0 += 64){
    for (int i = tid; i < 64*DIMH; i += 256){
      int rr = i / DIMH, d = i % DIMH;
      int kr = k0 + rr;
      Vs[rr][d] = (kr < kend) ? Vp[(size_t)kr*DIMH + d] : 0.f;
    }
    for (int i = tid; i < 4096; i += 256){
      int qq = i >> 6, kk = i & 63;
      int kr = k0 + kk;
      Ps[qq][kk] = (kr < kend)
          ? __expf(Sbh[(size_t)lqS[qq]*LL + kr]*sc - rowm[qq]) : 0.f;
    }
    __syncthreads();
#pragma unroll 4
    for (int kk = 0; kk < 64; kk++){
      float p = Ps[r][kk];
      ssum += p;
#pragma unroll
      for (int c = 0; c < 9; c++) acc[c] += p * Vs[kk][cg*9 + c];
    }
    __syncthreads();
  }
  if (q0 + r < NQ_){
    size_t qo = ((size_t)ksb*BHN + bh)*NQ_ + q0 + r;
    float* dst = g_opart + qo*DIMH + cg*9;
#pragma unroll
    for (int c = 0; c < 9; c++) dst[c] = acc[c];
    if (cg == 0){ g_ms[qo] = rowm[r]; g_ss[qo] = ssum; }
  }
}

// ---------------- vmean ----------------
__global__ void vmean_k(){
  __shared__ float sm[32];
  int d = blockIdx.x, bh = blockIdx.y, t = threadIdx.x;
  float s = 0.f;
  for (int l = t; l < LL; l += 256) s += g_v[((size_t)bh*LL + l)*DIMH + d];
  s = blockRedSum(s, sm, 8);
  if (t == 0) g_vmean[bh*DIMH + d] = s * (1.0f/(float)LL);
}

// ---------------- LN1 fused: combine split-softmax partials (or vmean) + x, then LN ----------------
__global__ void ln1f_kernel(const float* __restrict__ x,
                            const float* __restrict__ gamma, const float* __restrict__ beta,
                            float* __restrict__ out){
  __shared__ float2 sm[32];
  int row = blockIdx.x, t = threadIdx.x;
  int b_ = row / LL, l = row % LL;
  int h = t / DIMH, d = t % DIMH;
  int bh = b_*HH + h;
  int qi = g_inv[bh*LL + l];
  float attn;
  if (qi >= 0){
    float m4[KSPLIT], s4[KSPLIT];
    float M = -INFINITY;
#pragma unroll
    for (int ks = 0; ks < KSPLIT; ks++){
      size_t qo = ((size_t)ks*BHN + bh)*NQ_ + qi;
      m4[ks] = g_ms[qo]; s4[ks] = g_ss[qo];
      M = fmaxf(M, m4[ks]);
    }
    float denom = 0.f, a = 0.f;
#pragma unroll
    for (int ks = 0; ks < KSPLIT; ks++){
      float wgt = __expf(m4[ks] - M);
      denom += s4[ks]*wgt;
      a += g_opart[(((size_t)ks*BHN + bh)*NQ_ + qi)*DIMH + d]*wgt;
    }
    attn = a / denom;
  } else {
    attn = g_vmean[bh*DIMH + d];
  }
  float s = x[(size_t)row*DD + t] + attn;
  float2 red = blockRedSum2(s, s*s, sm, 9);
  float mu = red.x * (1.0f/(float)DD);
  float var = red.y * (1.0f/(float)DD) - mu*mu;
  out[(size_t)row*DD + t] = (s - mu) * rsqrtf(var + 1e-5f) * gamma[t] + beta[t];
}

// ---------------- LN2: sum ffn2 partials + bias -> GELU -> +h1 -> LN (single-pass) ----------------
__global__ void ln2_kernel(const float* __restrict__ f2p, const float* __restrict__ b2,
                           const float* __restrict__ h1,
                           const float* __restrict__ gamma, const float* __restrict__ beta,
                           float* __restrict__ out){
  __shared__ float2 sm[32];
  int row = blockIdx.x, t = threadIdx.x;
  size_t o = (size_t)row*DD + t;
  const size_t stride = (size_t)BB*LL*DD;
  float v = f2p[o] + f2p[stride + o] + f2p[2*stride + o] + b2[t];
  v = 0.5f*v*(1.0f + erff(v*0.70710678118654752f));
  float s = v + h1[o];
  float2 red = blockRedSum2(s, s*s, sm, 9);
  float mu = red.x * (1.0f/(float)DD);
  float var = red.y * (1.0f/(float)DD) - mu*mu;
  out[o] = (s - mu) * rsqrtf(var + 1e-5f) * gamma[t] + beta[t];
}

// ---------------- launch ----------------
extern "C" void kernel_launch(void* const* d_in, const int* in_sizes, int n_in,
                              void* d_out, int out_size){
  const float* x  = (const float*)d_in[0];
  const int*   ik = (const int*)  d_in[1];
  const float* Wq = (const float*)d_in[2];  const float* bq = (const float*)d_in[3];
  const float* Wk = (const float*)d_in[4];  const float* bk = (const float*)d_in[5];
  const float* Wv = (const float*)d_in[6];  const float* bv = (const float*)d_in[7];
  const float* W1 = (const float*)d_in[8];  const float* b1 = (const float*)d_in[9];
  const float* W2 = (const float*)d_in[10]; const float* b2 = (const float*)d_in[11];
  const float* g1 = (const float*)d_in[12]; const float* be1 = (const float*)d_in[13];
  const float* g2 = (const float*)d_in[14]; const float* be2 = (const float*)d_in[15];
  float* out = (float*)d_out;

  float *pq, *pk, *pv, *ph1, *pf1, *pf2;
  cudaGetSymbolAddress((void**)&pq,   g_q);
  cudaGetSymbolAddress((void**)&pk,   g_k);
  cudaGetSymbolAddress((void**)&pv,   g_v);
  cudaGetSymbolAddress((void**)&ph1,  g_h1);
  cudaGetSymbolAddress((void**)&pf1,  g_f1);
  cudaGetSymbolAddress((void**)&pf2,  g_f2);

  const int M = BB*LL;  // 2000
  qkv_k<<<dim3(DD/96, (M + 127)/128, 3), 256>>>(x, Wq, bq, Wk, bk, Wv, bv, pq, pk, pv);

  sgemm128<<<dim3(8, 8, BHN), 256>>>();
  measure_k<<<dim3((LL + 7)/8, BHN), 256>>>(ik);
  topk_k<<<BHN, 256>>>();
  spv_k<<<dim3((NQ_ + 63)/64, KSPLIT, BHN), 256>>>();
  vmean_k<<<dim3(DIMH, BHN), 256>>>();

  ln1f_kernel<<<M, DD>>>(x, g1, be1, ph1);

  ffn1_k<<<dim3(DFF_/96, (M + 63)/64), 128>>>(ph1, W1, b1, pf1);
  ffn2_k<<<dim3(DD/96, (M + 127)/128, FSPLIT), 256>>>(pf1, W2, pf2);

  ln2_kernel<<<M, DD>>>(pf2, b2, ph1, g2, be2, out);
}

// round 15
// speedup vs baseline: 1.2287x; 1.1409x over previous
#include <cuda_runtime.h>
#include <cuda_bf16.h>
#include <cstdint>
#include <math.h>

#define BB 2
#define LL 1000
#define DD 288
#define HH 8
#define DIMH 36
#define DFF_ 576
#define KS_ 250
#define NQ_ 250
#define BHN 16   // BB*HH
#define KSPLIT 4
#define FSPLIT 3   // ffn2 k-split

// ---------------- scratch (device globals; no allocs allowed) ----------------
__device__ __align__(16) float g_q[BHN*LL*DIMH];
__device__ __align__(16) float g_k[BHN*LL*DIMH];
__device__ __align__(16) float g_v[BHN*LL*DIMH];
__device__ __align__(16) float g_S[(size_t)BHN*LL*LL];      // 64 MB
__device__ float g_meas[BHN*LL];
__device__ int   g_idxq[BHN*NQ_];
__device__ int   g_inv[BHN*LL];
__device__ float g_opart[(size_t)KSPLIT*BHN*NQ_*DIMH];
__device__ float g_ms[KSPLIT*BHN*NQ_];
__device__ float g_ss[KSPLIT*BHN*NQ_];
__device__ float g_vmean[BHN*DIMH];
__device__ __align__(16) float g_h1[BB*LL*DD];
__device__ __align__(16) float g_f1[BB*LL*DFF_];
__device__ __align__(16) float g_f2[(size_t)FSPLIT*BB*LL*DD];

// ---------------- mma.sync helpers ----------------
__device__ __forceinline__ uint32_t smem_u32(const void* p){
  uint32_t a;
  asm("{ .reg .u64 t; cvta.to.shared.u64 t, %1; cvt.u32.u64 %0, t; }" : "=r"(a) : "l"(p));
  return a;
}
__device__ __forceinline__ void ldsm_x4(uint32_t& r0, uint32_t& r1, uint32_t& r2, uint32_t& r3, uint32_t addr){
  asm volatile("ldmatrix.sync.aligned.m8n8.x4.shared.b16 {%0,%1,%2,%3}, [%4];"
    : "=r"(r0),"=r"(r1),"=r"(r2),"=r"(r3) : "r"(addr));
}
__device__ __forceinline__ void mma16816(float* c, const uint32_t* a, const uint32_t* b){
  asm volatile("mma.sync.aligned.m16n8k16.row.col.f32.bf16.bf16.f32 "
    "{%0,%1,%2,%3}, {%4,%5,%6,%7}, {%8,%9}, {%0,%1,%2,%3};"
    : "+f"(c[0]),"+f"(c[1]),"+f"(c[2]),"+f"(c[3])
    : "r"(a[0]),"r"(a[1]),"r"(a[2]),"r"(a[3]), "r"(b[0]),"r"(b[1]));
}

// ---------------- reduction helpers ----------------
__device__ __forceinline__ float warpRedSum(float v){
#pragma unroll
  for (int o=16;o;o>>=1) v += __shfl_xor_sync(0xffffffffu, v, o);
  return v;
}
__device__ __forceinline__ float warpRedMax(float v){
#pragma unroll
  for (int o=16;o;o>>=1) v = fmaxf(v, __shfl_xor_sync(0xffffffffu, v, o));
  return v;
}
__device__ float blockRedSum(float v, float* sm, int nwarp){
  int w = threadIdx.x >> 5, lane = threadIdx.x & 31;
  v = warpRedSum(v);
  if (lane == 0) sm[w] = v;
  __syncthreads();
  float r;
  if (w == 0){
    r = (lane < nwarp) ? sm[lane] : 0.f;
    r = warpRedSum(r);
    if (lane == 0) sm[0] = r;
  }
  __syncthreads();
  r = sm[0];
  __syncthreads();
  return r;
}
__device__ float2 blockRedSum2(float a, float b, float2* sm, int nwarp){
  int w = threadIdx.x >> 5, lane = threadIdx.x & 31;
#pragma unroll
  for (int o=16;o;o>>=1){
    a += __shfl_xor_sync(0xffffffffu, a, o);
    b += __shfl_xor_sync(0xffffffffu, b, o);
  }
  if (lane == 0) sm[w] = make_float2(a, b);
  __syncthreads();
  float2 r;
  if (w == 0){
    float ra = (lane < nwarp) ? sm[lane].x : 0.f;
    float rb = (lane < nwarp) ? sm[lane].y : 0.f;
#pragma unroll
    for (int o=16;o;o>>=1){
      ra += __shfl_xor_sync(0xffffffffu, ra, o);
      rb += __shfl_xor_sync(0xffffffffu, rb, o);
    }
    if (lane == 0) sm[0] = make_float2(ra, rb);
  }
  __syncthreads();
  r = sm[0];
  __syncthreads();
  return r;
}

// ============ fp32 GEMM (qkv only): 128x96 tile, 8x6 micro ============
template<int MODE, int GELU, int BIAS>
__device__ __forceinline__ void gemm_body(const float* __restrict__ A, const float* __restrict__ W,
                                          const float* __restrict__ bias, float* __restrict__ C,
                                          int M, int N, int lda, int kStart, int kLen){
  const int NT = 256;
  const int RS = 16;
  __shared__ __align__(16) float As[128][36];
  __shared__ float Bs[32][97];
  int tid = threadIdx.x;
  int m0 = blockIdx.y * 128, n0 = blockIdx.x * 96;
  int tx = tid & 15, ty = tid >> 4;
  float acc[8][6] = {};
  float4 ra[4], rb[3];
  const float4 z4 = make_float4(0.f,0.f,0.f,0.f);

#pragma unroll
  for (int it = 0; it < 4; it++){
    int i = tid + it*NT;
    int m = i >> 3, kv = i & 7;
    int gm = m0 + m;
    ra[it] = (gm < M) ? *(const float4*)(A + (size_t)gm*lda + kStart + 4*kv) : z4;
  }
#pragma unroll
  for (int it = 0; it < 3; it++){
    int i = tid + it*NT;
    int n = i >> 3, kv = i & 7;
    rb[it] = *(const float4*)(W + (size_t)(n0 + n)*lda + kStart + 4*kv);
  }
#pragma unroll
  for (int it = 0; it < 4; it++){
    int i = tid + it*NT;
    int m = i >> 3, kv = i & 7;
    *(float4*)(&As[m][4*kv]) = ra[it];
  }
#pragma unroll
  for (int it = 0; it < 3; it++){
    int i = tid + it*NT;
    int n = i >> 3, kv = i & 7;
    Bs[4*kv+0][n] = rb[it].x; Bs[4*kv+1][n] = rb[it].y;
    Bs[4*kv+2][n] = rb[it].z; Bs[4*kv+3][n] = rb[it].w;
  }
  __syncthreads();

  for (int k0 = 0; k0 < kLen; k0 += 32){
    bool more = (k0 + 32) < kLen;
    if (more){
      int kg = kStart + k0 + 32;
#pragma unroll
      for (int it = 0; it < 4; it++){
        int i = tid + it*NT;
        int m = i >> 3, kv = i & 7;
        int gm = m0 + m;
        ra[it] = (gm < M) ? *(const float4*)(A + (size_t)gm*lda + kg + 4*kv) : z4;
      }
#pragma unroll
      for (int it = 0; it < 3; it++){
        int i = tid + it*NT;
        int n = i >> 3, kv = i & 7;
        rb[it] = *(const float4*)(W + (size_t)(n0 + n)*lda + kg + 4*kv);
      }
    }
#pragma unroll 4
    for (int kk = 0; kk < 32; kk++){
      float a[8], b[6];
#pragma unroll
      for (int i = 0; i < 8; i++) a[i] = As[ty + RS*i][kk];
#pragma unroll
      for (int j = 0; j < 6; j++) b[j] = Bs[kk][tx*6+j];
#pragma unroll
      for (int i = 0; i < 8; i++)
#pragma unroll
        for (int j = 0; j < 6; j++) acc[i][j] += a[i]*b[j];
    }
    __syncthreads();
    if (more){
#pragma unroll
      for (int it = 0; it < 4; it++){
        int i = tid + it*NT;
        int m = i >> 3, kv = i & 7;
        *(float4*)(&As[m][4*kv]) = ra[it];
      }
#pragma unroll
      for (int it = 0; it < 3; it++){
        int i = tid + it*NT;
        int n = i >> 3, kv = i & 7;
        Bs[4*kv+0][n] = rb[it].x; Bs[4*kv+1][n] = rb[it].y;
        Bs[4*kv+2][n] = rb[it].z; Bs[4*kv+3][n] = rb[it].w;
      }
      __syncthreads();
    }
  }
#pragma unroll
  for (int i = 0; i < 8; i++){
    int m = m0 + ty + RS*i;
    if (m >= M) continue;
#pragma unroll
    for (int j = 0; j < 6; j++){
      int n = n0 + tx*6 + j;
      float vv = acc[i][j];
      if (BIAS) vv += bias[n];
      if (GELU) vv = 0.5f*vv*(1.0f + erff(vv*0.70710678118654752f));
      if (MODE == 0){
        C[(size_t)m*N + n] = vv;
      } else {
        int b_ = m / LL, l = m % LL;
        int h = n / DIMH, d = n % DIMH;
        C[(((size_t)b_*HH + h)*LL + l)*DIMH + d] = vv;
      }
    }
  }
}

__global__ void __launch_bounds__(256) qkv_k(const float* __restrict__ x,
    const float* __restrict__ Wq, const float* __restrict__ bq,
    const float* __restrict__ Wk, const float* __restrict__ bk,
    const float* __restrict__ Wv, const float* __restrict__ bv,
    float* pq, float* pk, float* pv){
  const float* W; const float* b; float* C;
  if (blockIdx.z == 0){ W = Wq; b = bq; C = pq; }
  else if (blockIdx.z == 1){ W = Wk; b = bk; C = pk; }
  else { W = Wv; b = bv; C = pv; }
  gemm_body<1,0,1>(x, W, b, C, BB*LL, DD, DD, 0, DD);
}

// ============ tensor-core FFN GEMM: mma.sync bf16 hi/lo compensated ============
// Block 128x96, 8 warps (4m x 2n), warp tile 32x48. kLen % 32 == 0.
template<int GELU, int BIAS>
__device__ __forceinline__ void tmma_body(const float* __restrict__ A, const float* __restrict__ W,
                                          const float* __restrict__ bias, float* __restrict__ C,
                                          int M, int Ntot, int lda, int kStart, int kLen){
  __shared__ __align__(16) __nv_bfloat16 Ah[128][40];
  __shared__ __align__(16) __nv_bfloat16 Al[128][40];
  __shared__ __align__(16) __nv_bfloat16 Bh[96][40];
  __shared__ __align__(16) __nv_bfloat16 Bl[96][40];
  int tid = threadIdx.x, wid = tid >> 5, lid = tid & 31;
  int m0 = blockIdx.y*128, n0 = blockIdx.x*96;
  int wm = wid & 3, wn = wid >> 2;
  int m0w = wm*32, n0w = wn*48;
  float acc[2][6][4] = {};
  float4 ra[4], rb[3];
  const float4 z4 = make_float4(0.f,0.f,0.f,0.f);

  int NCH = kLen / 32;
#pragma unroll 1
  for (int ch = 0; ch < NCH + 1; ch++){
    // load next chunk into regs (chunks 0..NCH-1)
    if (ch < NCH){
      int kg = kStart + ch*32;
#pragma unroll
      for (int it = 0; it < 4; it++){
        int i = tid + it*256, row = i >> 3, kv = i & 7;
        int gm = m0 + row;
        ra[it] = (gm < M) ? *(const float4*)(A + (size_t)gm*lda + kg + 4*kv) : z4;
      }
#pragma unroll
      for (int it = 0; it < 3; it++){
        int i = tid + it*256, row = i >> 3, kv = i & 7;
        rb[it] = *(const float4*)(W + (size_t)(n0 + row)*lda + kg + 4*kv);
      }
    }
    // compute on previous chunk (chunks 1..NCH)
    if (ch > 0){
#pragma unroll
      for (int ks = 0; ks < 32; ks += 16){
        uint32_t ah[2][4], al[2][4];
#pragma unroll
        for (int mt = 0; mt < 2; mt++){
          int rr = m0w + mt*16 + (lid & 7) + ((lid >> 3) & 1)*8;
          int cc = ks + ((lid >> 4) & 1)*8;
          ldsm_x4(ah[mt][0],ah[mt][1],ah[mt][2],ah[mt][3], smem_u32(&Ah[rr][cc]));
          ldsm_x4(al[mt][0],al[mt][1],al[mt][2],al[mt][3], smem_u32(&Al[rr][cc]));
        }
        uint32_t bhf[6][2], blf[6][2];
#pragma unroll
        for (int j = 0; j < 3; j++){
          int rr = n0w + j*16 + (lid & 7) + ((lid >> 4) & 1)*8;
          int cc = ks + ((lid >> 3) & 1)*8;
          uint32_t r0,r1,r2,r3;
          ldsm_x4(r0,r1,r2,r3, smem_u32(&Bh[rr][cc]));
          bhf[2*j][0]=r0; bhf[2*j][1]=r1; bhf[2*j+1][0]=r2; bhf[2*j+1][1]=r3;
          ldsm_x4(r0,r1,r2,r3, smem_u32(&Bl[rr][cc]));
          blf[2*j][0]=r0; blf[2*j][1]=r1; blf[2*j+1][0]=r2; blf[2*j+1][1]=r3;
        }
#pragma unroll
        for (int mt = 0; mt < 2; mt++)
#pragma unroll
          for (int nt = 0; nt < 6; nt++){
            mma16816(acc[mt][nt], ah[mt], bhf[nt]);
            mma16816(acc[mt][nt], ah[mt], blf[nt]);
            mma16816(acc[mt][nt], al[mt], bhf[nt]);
          }
      }
      __syncthreads();   // done reading smem
    }
    // convert + store regs into smem for next compute
    if (ch < NCH){
#pragma unroll
      for (int it = 0; it < 4; it++){
        int i = tid + it*256, row = i >> 3, kv = i & 7;
        float vv[4] = {ra[it].x, ra[it].y, ra[it].z, ra[it].w};
        __nv_bfloat16 h[4], l[4];
#pragma unroll
        for (int c = 0; c < 4; c++){
          h[c] = __float2bfloat16(vv[c]);
          l[c] = __float2bfloat16(vv[c] - __bfloat162float(h[c]));
        }
        *(__nv_bfloat162*)(&Ah[row][4*kv])   = __halves2bfloat162(h[0],h[1]);
        *(__nv_bfloat162*)(&Ah[row][4*kv+2]) = __halves2bfloat162(h[2],h[3]);
        *(__nv_bfloat162*)(&Al[row][4*kv])   = __halves2bfloat162(l[0],l[1]);
        *(__nv_bfloat162*)(&Al[row][4*kv+2]) = __halves2bfloat162(l[2],l[3]);
      }
#pragma unroll
      for (int it = 0; it < 3; it++){
        int i = tid + it*256, row = i >> 3, kv = i & 7;
        float vv[4] = {rb[it].x, rb[it].y, rb[it].z, rb[it].w};
        __nv_bfloat16 h[4], l[4];
#pragma unroll
        for (int c = 0; c < 4; c++){
          h[c] = __float2bfloat16(vv[c]);
          l[c] = __float2bfloat16(vv[c] - __bfloat162float(h[c]));
        }
        *(__nv_bfloat162*)(&Bh[row][4*kv])   = __halves2bfloat162(h[0],h[1]);
        *(__nv_bfloat162*)(&Bh[row][4*kv+2]) = __halves2bfloat162(h[2],h[3]);
        *(__nv_bfloat162*)(&Bl[row][4*kv])   = __halves2bfloat162(l[0],l[1]);
        *(__nv_bfloat162*)(&Bl[row][4*kv+2]) = __halves2bfloat162(l[2],l[3]);
      }
      __syncthreads();
    }
  }
  // epilogue
  int g = lid >> 2, tp = lid & 3;
#pragma unroll
  for (int mt = 0; mt < 2; mt++){
#pragma unroll
    for (int half = 0; half < 2; half++){
      int m = m0 + m0w + mt*16 + g + half*8;
      if (m >= M) continue;
#pragma unroll
      for (int nt = 0; nt < 6; nt++){
        int n = n0 + n0w + nt*8 + tp*2;
        float v0 = acc[mt][nt][half*2+0];
        float v1 = acc[mt][nt][half*2+1];
        if (BIAS){ v0 += bias[n]; v1 += bias[n+1]; }
        if (GELU){
          v0 = 0.5f*v0*(1.0f + erff(v0*0.70710678118654752f));
          v1 = 0.5f*v1*(1.0f + erff(v1*0.70710678118654752f));
        }
        *(float2*)(&C[(size_t)m*Ntot + n]) = make_float2(v0, v1);
      }
    }
  }
}

__global__ void __launch_bounds__(256) ffn1_t(const float* __restrict__ A, const float* __restrict__ W,
                                              const float* __restrict__ bias, float* __restrict__ C){
  tmma_body<1,1>(A, W, bias, C, BB*LL, DFF_, DD, 0, DD);
}
__global__ void __launch_bounds__(256) ffn2_t(const float* __restrict__ A, const float* __restrict__ W,
                                              float* __restrict__ C){
  int ks = blockIdx.z;
  const int kLen = DFF_/FSPLIT;   // 192
  tmma_body<0,0>(A, W, nullptr, C + (size_t)ks*BB*LL*DD, BB*LL, DD, DFF_, ks*kLen, kLen);
}

// ---------------- S = Q K^T per (b,h): 128x128 tile, 8x8 micro (fp32) ----------------
__global__ void __launch_bounds__(256) sgemm128(){
  __shared__ __align__(16) float QsT[DIMH][132];
  __shared__ __align__(16) float KsT[DIMH][132];
  int bh = blockIdx.z;
  int q0 = blockIdx.y*128, k0 = blockIdx.x*128;
  const float* Q  = g_q + (size_t)bh*LL*DIMH;
  const float* Kp = g_k + (size_t)bh*LL*DIMH;
  int tid = threadIdx.x;
  const float4 z4 = make_float4(0.f,0.f,0.f,0.f);
  for (int i = tid; i < 1152; i += 256){
    int r = i / 9, dv = i % 9;
    int gq = q0 + r, gk = k0 + r;
    float4 vq = (gq < LL) ? *(const float4*)(Q  + (size_t)gq*DIMH + 4*dv) : z4;
    float4 vk = (gk < LL) ? *(const float4*)(Kp + (size_t)gk*DIMH + 4*dv) : z4;
    QsT[4*dv+0][r] = vq.x; QsT[4*dv+1][r] = vq.y; QsT[4*dv+2][r] = vq.z; QsT[4*dv+3][r] = vq.w;
    KsT[4*dv+0][r] = vk.x; KsT[4*dv+1][r] = vk.y; KsT[4*dv+2][r] = vk.z; KsT[4*dv+3][r] = vk.w;
  }
  __syncthreads();
  int tx = tid & 15, ty = tid >> 4;
  float acc[8][8] = {};
#pragma unroll 4
  for (int d = 0; d < DIMH; d++){
    float4 a0 = *(const float4*)(&QsT[d][ty*8]);
    float4 a1 = *(const float4*)(&QsT[d][ty*8+4]);
    float4 b0 = *(const float4*)(&KsT[d][tx*8]);
    float4 b1 = *(const float4*)(&KsT[d][tx*8+4]);
    float a[8] = {a0.x,a0.y,a0.z,a0.w,a1.x,a1.y,a1.z,a1.w};
    float b[8] = {b0.x,b0.y,b0.z,b0.w,b1.x,b1.y,b1.z,b1.w};
#pragma unroll
    for (int i = 0; i < 8; i++)
#pragma unroll
      for (int j = 0; j < 8; j++) acc[i][j] += a[i]*b[j];
  }
  float* Sp = g_S + (size_t)bh*LL*LL;
  bool fullcol = (k0 + tx*8 + 7) < LL;
#pragma unroll
  for (int i = 0; i < 8; i++){
    int m = q0 + ty*8 + i;
    if (m >= LL) continue;
    float* dst = Sp + (size_t)m*LL + k0 + tx*8;
    if (fullcol){
      *(float4*)dst      = make_float4(acc[i][0],acc[i][1],acc[i][2],acc[i][3]);
      *(float4*)(dst+4)  = make_float4(acc[i][4],acc[i][5],acc[i][6],acc[i][7]);
    } else {
#pragma unroll
      for (int j = 0; j < 8; j++)
        if (k0 + tx*8 + j < LL) dst[j] = acc[i][j];
    }
  }
}

// ---------------- measure (warp/row) ----------------
__global__ void measure_k(const int* __restrict__ ik){
  int w = threadIdx.x >> 5, lane = threadIdx.x & 31;
  int l = blockIdx.x*8 + w, bh = blockIdx.y;
  if (l >= LL) return;
  const float* Srow = g_S + ((size_t)bh*LL + l)*LL;
  const int* row = ik + l*KS_;
  float mx = -INFINITY, s = 0.f;
  for (int j = lane; j < KS_; j += 32){
    float vv = Srow[row[j]];
    mx = fmaxf(mx, vv); s += vv;
  }
  mx = warpRedMax(mx);
  s  = warpRedSum(s);
  if (lane == 0) g_meas[bh*LL + l] = mx - s * (1.0f/(float)LL);
}

// ---------------- top-NQ per (b,h): register radix select ----------------
__global__ void __launch_bounds__(256) topk_k(){
  __shared__ int hist[256];
  __shared__ int warpbase[9];
  __shared__ int s_digit, s_r;
  int bh = blockIdx.x, tid = threadIdx.x;
  bool real = tid < 250;
  unsigned kv[4] = {0,0,0,0};
  if (real){
#pragma unroll
    for (int j = 0; j < 4; j++){
      unsigned u = __float_as_uint(g_meas[bh*LL + 4*tid + j]);
      kv[j] = (u & 0x80000000u) ? ~u : (u | 0x80000000u);
    }
  }
  hist[tid] = 0;
  __syncthreads();
  unsigned prefix = 0; int r = NQ_;
#pragma unroll
  for (int pass = 0; pass < 4; pass++){
    int shift = 24 - pass*8;
    if (real){
#pragma unroll
      for (int j = 0; j < 4; j++){
        unsigned u = kv[j];
        if (pass == 0 || (u >> (shift + 8)) == prefix)
          atomicAdd(&hist[(u >> shift) & 255], 1);
      }
    }
    __syncthreads();
    if (tid < 32){
      int b[8], suf[8]; int acc = 0;
#pragma unroll
      for (int j = 7; j >= 0; j--){ b[j] = hist[tid*8 + j]; acc += b[j]; suf[j] = acc; }
      int inc = acc;
#pragma unroll
      for (int off = 1; off < 32; off <<= 1){
        int t = __shfl_down_sync(0xffffffffu, inc, off);
        if (tid + off < 32) inc += t;
      }
      int hiex = inc - acc;
#pragma unroll
      for (int j = 0; j < 8; j++){
        int ge = suf[j] + hiex;
        int gt = ge - b[j];
        if (gt < r && r <= ge){ s_digit = tid*8 + j; s_r = r - gt; }
      }
    }
    __syncthreads();
    prefix = (prefix << 8) | (unsigned)s_digit;
    r = s_r;
    hist[tid] = 0;
    __syncthreads();
  }
  unsigned T = prefix;
  int cg = 0, ce = 0; int locg[4], loce[4];
  if (real){
#pragma unroll
    for (int j = 0; j < 4; j++){
      locg[j] = cg; loce[j] = ce;
      cg += (kv[j] > T); ce += (kv[j] == T);
    }
  }
  int pack = (cg << 16) | ce;
  int lane = tid & 31, w = tid >> 5;
  int sc = pack;
#pragma unroll
  for (int off = 1; off < 32; off <<= 1){
    int t = __shfl_up_sync(0xffffffffu, sc, off);
    if (lane >= off) sc += t;
  }
  if (lane == 31) warpbase[w+1] = sc;
  if (tid == 0) warpbase[0] = 0;
  __syncthreads();
  if (tid == 0){ for (int i = 1; i < 8; i++) warpbase[i+1] += warpbase[i]; }
  __syncthreads();
  int excl = sc - pack + warpbase[w];
  int eg = excl >> 16, ee = excl & 0xffff;
  if (real){
#pragma unroll
    for (int j = 0; j < 4; j++){
      int i = 4*tid + j;
      int pos = -1;
      if (kv[j] > T) pos = eg + locg[j];
      else if (kv[j] == T){
        int rk = ee + loce[j];
        if (rk < r) pos = (NQ_ - r) + rk;
      }
      g_inv[bh*LL + i] = pos;
      if (pos >= 0) g_idxq[bh*NQ_ + pos] = i;
    }
  }
}

// ---------------- fused ONLINE softmax + PV per k-split (bounds-guarded) ----------------
__global__ void __launch_bounds__(256) spv_k(){
  __shared__ float Ps[64][65];
  __shared__ float Vs[64][37];
  __shared__ float rowm[64];
  __shared__ int   lqS[64];
  int tid = threadIdx.x;
  int q0 = blockIdx.x*64;
  int ksb = blockIdx.y;
  int bh = blockIdx.z;
  int kstart = ksb*(LL/KSPLIT), kend = kstart + (LL/KSPLIT);
  const float sc = 1.0f/6.0f;
  if (tid < 64){
    int gq = q0 + tid;
    lqS[tid] = (gq < NQ_) ? g_idxq[bh*NQ_ + gq] : 0;
  }
  __syncthreads();
  const float* Vp = g_v + (size_t)bh*LL*DIMH;
  const float* Sbh = g_S + (size_t)bh*LL*LL;
  int r = tid >> 2, cg = tid & 3;
  {
    const float* row = Sbh + (size_t)lqS[r]*LL;
    float mx = -INFINITY;
    for (int c = kstart + cg; c < kend; c += 4) mx = fmaxf(mx, row[c]);
    mx = fmaxf(mx, __shfl_xor_sync(0xffffffffu, mx, 1));
    mx = fmaxf(mx, __shfl_xor_sync(0xffffffffu, mx, 2));
    if (cg == 0) rowm[r] = mx * sc;
  }
  __syncthreads();
  float acc[9] = {};
  float ssum = 0.f;
  for (int k0 = kstart; k0 < kend; k0 += 64){
    for (int i = tid; i < 64*DIMH; i += 256){
      int rr = i / DIMH, d = i % DIMH;
      int kr = k0 + rr;
      Vs[rr][d] = (kr < kend) ? Vp[(size_t)kr*DIMH + d] : 0.f;
    }
    for (int i = tid; i < 4096; i += 256){
      int qq = i >> 6, kk = i & 63;
      int kr = k0 + kk;
      Ps[qq][kk] = (kr < kend)
          ? __expf(Sbh[(size_t)lqS[qq]*LL + kr]*sc - rowm[qq]) : 0.f;
    }
    __syncthreads();
#pragma unroll 4
    for (int kk = 0; kk < 64; kk++){
      float p = Ps[r][kk];
      ssum += p;
#pragma unroll
      for (int c = 0; c < 9; c++) acc[c] += p * Vs[kk][cg*9 + c];
    }
    __syncthreads();
  }
  if (q0 + r < NQ_){
    size_t qo = ((size_t)ksb*BHN + bh)*NQ_ + q0 + r;
    float* dst = g_opart + qo*DIMH + cg*9;
#pragma unroll
    for (int c = 0; c < 9; c++) dst[c] = acc[c];
    if (cg == 0){ g_ms[qo] = rowm[r]; g_ss[qo] = ssum; }
  }
}

// ---------------- vmean ----------------
__global__ void vmean_k(){
  __shared__ float sm[32];
  int d = blockIdx.x, bh = blockIdx.y, t = threadIdx.x;
  float s = 0.f;
  for (int l = t; l < LL; l += 256) s += g_v[((size_t)bh*LL + l)*DIMH + d];
  s = blockRedSum(s, sm, 8);
  if (t == 0) g_vmean[bh*DIMH + d] = s * (1.0f/(float)LL);
}

// ---------------- LN1 fused ----------------
__global__ void ln1f_kernel(const float* __restrict__ x,
                            const float* __restrict__ gamma, const float* __restrict__ beta,
                            float* __restrict__ out){
  __shared__ float2 sm[32];
  int row = blockIdx.x, t = threadIdx.x;
  int b_ = row / LL, l = row % LL;
  int h = t / DIMH, d = t % DIMH;
  int bh = b_*HH + h;
  int qi = g_inv[bh*LL + l];
  float attn;
  if (qi >= 0){
    float m4[KSPLIT], s4[KSPLIT];
    float M = -INFINITY;
#pragma unroll
    for (int ks = 0; ks < KSPLIT; ks++){
      size_t qo = ((size_t)ks*BHN + bh)*NQ_ + qi;
      m4[ks] = g_ms[qo]; s4[ks] = g_ss[qo];
      M = fmaxf(M, m4[ks]);
    }
    float denom = 0.f, a = 0.f;
#pragma unroll
    for (int ks = 0; ks < KSPLIT; ks++){
      float wgt = __expf(m4[ks] - M);
      denom += s4[ks]*wgt;
      a += g_opart[(((size_t)ks*BHN + bh)*NQ_ + qi)*DIMH + d]*wgt;
    }
    attn = a / denom;
  } else {
    attn = g_vmean[bh*DIMH + d];
  }
  float s = x[(size_t)row*DD + t] + attn;
  float2 red = blockRedSum2(s, s*s, sm, 9);
  float mu = red.x * (1.0f/(float)DD);
  float var = red.y * (1.0f/(float)DD) - mu*mu;
  out[(size_t)row*DD + t] = (s - mu) * rsqrtf(var + 1e-5f) * gamma[t] + beta[t];
}

// ---------------- LN2: sum ffn2 partials + bias -> GELU -> +h1 -> LN ----------------
__global__ void ln2_kernel(const float* __restrict__ f2p, const float* __restrict__ b2,
                           const float* __restrict__ h1,
                           const float* __restrict__ gamma, const float* __restrict__ beta,
                           float* __restrict__ out){
  __shared__ float2 sm[32];
  int row = blockIdx.x, t = threadIdx.x;
  size_t o = (size_t)row*DD + t;
  const size_t stride = (size_t)BB*LL*DD;
  float v = f2p[o] + f2p[stride + o] + f2p[2*stride + o] + b2[t];
  v = 0.5f*v*(1.0f + erff(v*0.70710678118654752f));
  float s = v + h1[o];
  float2 red = blockRedSum2(s, s*s, sm, 9);
  float mu = red.x * (1.0f/(float)DD);
  float var = red.y * (1.0f/(float)DD) - mu*mu;
  out[o] = (s - mu) * rsqrtf(var + 1e-5f) * gamma[t] + beta[t];
}

// ---------------- launch ----------------
extern "C" void kernel_launch(void* const* d_in, const int* in_sizes, int n_in,
                              void* d_out, int out_size){
  const float* x  = (const float*)d_in[0];
  const int*   ik = (const int*)  d_in[1];
  const float* Wq = (const float*)d_in[2];  const float* bq = (const float*)d_in[3];
  const float* Wk = (const float*)d_in[4];  const float* bk = (const float*)d_in[5];
  const float* Wv = (const float*)d_in[6];  const float* bv = (const float*)d_in[7];
  const float* W1 = (const float*)d_in[8];  const float* b1 = (const float*)d_in[9];
  const float* W2 = (const float*)d_in[10]; const float* b2 = (const float*)d_in[11];
  const float* g1 = (const float*)d_in[12]; const float* be1 = (const float*)d_in[13];
  const float* g2 = (const float*)d_in[14]; const float* be2 = (const float*)d_in[15];
  float* out = (float*)d_out;

  float *pq, *pk, *pv, *ph1, *pf1, *pf2;
  cudaGetSymbolAddress((void**)&pq,   g_q);
  cudaGetSymbolAddress((void**)&pk,   g_k);
  cudaGetSymbolAddress((void**)&pv,   g_v);
  cudaGetSymbolAddress((void**)&ph1,  g_h1);
  cudaGetSymbolAddress((void**)&pf1,  g_f1);
  cudaGetSymbolAddress((void**)&pf2,  g_f2);

  const int M = BB*LL;  // 2000
  qkv_k<<<dim3(DD/96, (M + 127)/128, 3), 256>>>(x, Wq, bq, Wk, bk, Wv, bv, pq, pk, pv);

  sgemm128<<<dim3(8, 8, BHN), 256>>>();
  measure_k<<<dim3((LL + 7)/8, BHN), 256>>>(ik);
  topk_k<<<BHN, 256>>>();
  spv_k<<<dim3((NQ_ + 63)/64, KSPLIT, BHN), 256>>>();
  vmean_k<<<dim3(DIMH, BHN), 256>>>();

  ln1f_kernel<<<M, DD>>>(x, g1, be1, ph1);

  ffn1_t<<<dim3(DFF_/96, (M + 127)/128), 256>>>(ph1, W1, b1, pf1);
  ffn2_t<<<dim3(DD/96, (M + 127)/128, FSPLIT), 256>>>(pf1, W2, pf2);

  ln2_kernel<<<M, DD>>>(pf2, b2, ph1, g2, be2, out);
}